// round 14
// baseline (speedup 1.0000x reference)
#include <cuda_runtime.h>
#include <cuda_fp16.h>

// ---------------------------------------------------------------------------
// Fused LEMURS actor, round 12:
//  LSU-wavefront bound (L1 ~69% invariant across R8-R10). Attack: fp16x2
//  attention.
//   - k,v stored as __half: one LDS.128 = 8 values (halves attention LDS wf)
//   - e = h2exp2(f16x2): ONE MUFU op per TWO exps (halves MUFU)
//   - t via __hmul2, num/den accumulated in 8 __half2 accums (depth<=8),
//     partials (<=32) converted to f32 for final sums (keeps rel_err ~3e-4)
//  Reverted: persistent work-steal grid (R10 neutral) -> plain 2048 blocks.
//  Rest identical to the 147.9us R8 structure.
// ---------------------------------------------------------------------------

#define RPB 8
#define NTHREADS 128

typedef unsigned long long u64;

__device__ float g_WinT[12 * 128];
__device__ float g_AqT1[128 * 128];
__device__ float g_AkT1[128 * 128];
__device__ float g_AvT1[128 * 128];
__device__ float g_WhT[128 * 64];
__device__ float g_AqT2[64 * 64];
__device__ float g_AkT2[64 * 64];
__device__ float g_AvT2[64 * 64];

__device__ __forceinline__ u64 pack2(float a, float b) {
    u64 r;
    asm("mov.b64 %0, {%1, %2};" : "=l"(r) : "f"(a), "f"(b));
    return r;
}
__device__ __forceinline__ void ffma2(u64& d, u64 a, u64 b) {
    asm("fma.rn.f32x2 %0, %1, %2, %0;" : "+l"(d) : "l"(a), "l"(b));
}
__device__ __forceinline__ float2 unpack2(u64 v) {
    float2 f;
    asm("mov.b64 {%0, %1}, %2;" : "=f"(f.x), "=f"(f.y) : "l"(v));
    return f;
}
__device__ __forceinline__ float siluf(float v) {
    return __fdividef(v, 1.0f + __expf(-v));
}
__device__ __forceinline__ __half2 h2r(unsigned u) {
    return *reinterpret_cast<__half2*>(&u);
}

__global__ void prep_weights(const float* __restrict__ Win,
                             const float* __restrict__ Aq1,
                             const float* __restrict__ Ak1,
                             const float* __restrict__ Av1,
                             const float* __restrict__ Wh,
                             const float* __restrict__ Aq2,
                             const float* __restrict__ Ak2,
                             const float* __restrict__ Av2) {
    int t = blockIdx.x * blockDim.x + threadIdx.x;
    int stride = gridDim.x * blockDim.x;
    for (int idx = t; idx < 128 * 12; idx += stride) {
        int i = idx / 12, j = idx - i * 12;
        g_WinT[j * 128 + i] = Win[idx];
    }
    for (int idx = t; idx < 128 * 128; idx += stride) {
        int i = idx >> 7, j = idx & 127;
        g_AqT1[j * 128 + i] = Aq1[idx];
        g_AkT1[j * 128 + i] = Ak1[idx];
        g_AvT1[j * 128 + i] = Av1[idx];
    }
    for (int idx = t; idx < 64 * 128; idx += stride) {
        int i = idx >> 7, j = idx & 127;
        g_WhT[j * 64 + i] = Wh[idx];
    }
    for (int idx = t; idx < 64 * 64; idx += stride) {
        int i = idx >> 6, j = idx & 63;
        g_AqT2[j * 64 + i] = Aq2[idx];
        g_AkT2[j * 64 + i] = Ak2[idx];
        g_AvT2[j * 64 + i] = Av2[idx];
    }
}

#define HSTR 12

// 16 exps in f16x2: 4 LDS.128 (8 k-halfs + 8 v-halfs per pair of uint4),
// 8 HMUL2, 8 MUFU(ex2.f16x2), 8 HFMA2, 8 HADD2.
#define ATTN_H16(kk0, kk1, vv0, vv1)                                          \
    {                                                                         \
        __half2 e;                                                            \
        e = h2exp2(__hmul2(qh, h2r((kk0).x)));                                \
        na[0] = __hfma2(e, h2r((vv0).x), na[0]); da[0] = __hadd2(da[0], e);   \
        e = h2exp2(__hmul2(qh, h2r((kk0).y)));                                \
        na[1] = __hfma2(e, h2r((vv0).y), na[1]); da[1] = __hadd2(da[1], e);   \
        e = h2exp2(__hmul2(qh, h2r((kk0).z)));                                \
        na[2] = __hfma2(e, h2r((vv0).z), na[2]); da[2] = __hadd2(da[2], e);   \
        e = h2exp2(__hmul2(qh, h2r((kk0).w)));                                \
        na[3] = __hfma2(e, h2r((vv0).w), na[3]); da[3] = __hadd2(da[3], e);   \
        e = h2exp2(__hmul2(qh, h2r((kk1).x)));                                \
        na[4] = __hfma2(e, h2r((vv1).x), na[4]); da[4] = __hadd2(da[4], e);   \
        e = h2exp2(__hmul2(qh, h2r((kk1).y)));                                \
        na[5] = __hfma2(e, h2r((vv1).y), na[5]); da[5] = __hadd2(da[5], e);   \
        e = h2exp2(__hmul2(qh, h2r((kk1).z)));                                \
        na[6] = __hfma2(e, h2r((vv1).z), na[6]); da[6] = __hadd2(da[6], e);   \
        e = h2exp2(__hmul2(qh, h2r((kk1).w)));                                \
        na[7] = __hfma2(e, h2r((vv1).w), na[7]); da[7] = __hadd2(da[7], e);   \
    }

// epilogue: pair accums (partials <= ~32), convert to f32, sum in f32
#define ATTN_EPI(numv, denv)                                                  \
    float numv, denv;                                                         \
    {                                                                         \
        __half2 s01 = __hadd2(na[0], na[1]), s23 = __hadd2(na[2], na[3]);     \
        __half2 s45 = __hadd2(na[4], na[5]), s67 = __hadd2(na[6], na[7]);     \
        float2 A = __half22float2(s01), B = __half22float2(s23);              \
        float2 C = __half22float2(s45), D = __half22float2(s67);              \
        numv = ((A.x + A.y) + (B.x + B.y)) + ((C.x + C.y) + (D.x + D.y));     \
        s01 = __hadd2(da[0], da[1]); s23 = __hadd2(da[2], da[3]);             \
        s45 = __hadd2(da[4], da[5]); s67 = __hadd2(da[6], da[7]);             \
        A = __half22float2(s01); B = __half22float2(s23);                     \
        C = __half22float2(s45); D = __half22float2(s67);                     \
        denv = ((A.x + A.y) + (B.x + B.y)) + ((C.x + C.y) + (D.x + D.y));     \
    }

__global__ __launch_bounds__(NTHREADS, 8)
void lemurs_fused(const float* __restrict__ x,
                  const float* __restrict__ b_in,
                  const float* __restrict__ Bq1, const float* __restrict__ Bk1,
                  const float* __restrict__ Bv1,
                  const float* __restrict__ b_h,
                  const float* __restrict__ Bq2, const float* __restrict__ Bk2,
                  const float* __restrict__ Bv2,
                  const float* __restrict__ Wout,
                  const float* __restrict__ b_out,
                  float* __restrict__ out) {
    __shared__ __align__(16) float sx[RPB * 12];
    __shared__ __align__(16) float shT[128 * HSTR];    // h1 -> attn1out
    __shared__ __align__(16) __half skh[RPB * 128];    // k (half) attn1/2
    __shared__ __align__(16) __half svh[RPB * 128];    // v (half)
    __shared__ __align__(16) float sh2T[64 * HSTR];    // h2
    __shared__ __align__(16) float sAt2[RPB * 64];     // attn2 out
    __shared__ float sy[RPB * 25];

    const int t = threadIdx.x;
    const int row0 = blockIdx.x * RPB;
    const float LOG2E = 1.4426950408889634f;

    if (t < RPB * 12) sx[t] = x[row0 * 12 + t];
    __syncthreads();

    const int i  = t;
    const int i2 = t & 63;
    const int g4 = t >> 6;

    // ---- phase 1: h1 = silu(x @ W_in^T + b_in) ----
    {
        float acc[8];
        float bb = b_in[i];
#pragma unroll
        for (int r = 0; r < 8; r++) acc[r] = bb;
#pragma unroll
        for (int j = 0; j < 12; j++) {
            float w = g_WinT[j * 128 + i];
#pragma unroll
            for (int r = 0; r < 8; r++)
                acc[r] += w * sx[r * 12 + j];
        }
        float4 o0 = make_float4(siluf(acc[0]), siluf(acc[1]),
                                siluf(acc[2]), siluf(acc[3]));
        float4 o1 = make_float4(siluf(acc[4]), siluf(acc[5]),
                                siluf(acc[6]), siluf(acc[7]));
        *(float4*)&shT[i * HSTR]     = o0;
        *(float4*)&shT[i * HSTR + 4] = o1;
    }
    __syncthreads();

    // ---- phase 2: q1,k1,v1 (128x128 GEMMs, f32x2); k,v stored as half ----
    float q[8];
    {
        u64 aq[4], ak[4], av[4];
        float bq = Bq1[i], bk = Bk1[i], bv = Bv1[i];
        u64 bq2 = pack2(bq, bq), bk2 = pack2(bk, bk), bv2 = pack2(bv, bv);
#pragma unroll
        for (int p = 0; p < 4; p++) { aq[p] = bq2; ak[p] = bk2; av[p] = bv2; }
#pragma unroll 4
        for (int j = 0; j < 128; j++) {
            float wq = g_AqT1[j * 128 + i];
            float wk = g_AkT1[j * 128 + i];
            float wv = g_AvT1[j * 128 + i];
            u64 wq2 = pack2(wq, wq), wk2 = pack2(wk, wk), wv2 = pack2(wv, wv);
            ulonglong2 ha = *(const ulonglong2*)&shT[j * HSTR];
            ulonglong2 hb = *(const ulonglong2*)&shT[j * HSTR + 4];
            ffma2(aq[0], wq2, ha.x); ffma2(aq[1], wq2, ha.y);
            ffma2(aq[2], wq2, hb.x); ffma2(aq[3], wq2, hb.y);
            ffma2(ak[0], wk2, ha.x); ffma2(ak[1], wk2, ha.y);
            ffma2(ak[2], wk2, hb.x); ffma2(ak[3], wk2, hb.y);
            ffma2(av[0], wv2, ha.x); ffma2(av[1], wv2, ha.y);
            ffma2(av[2], wv2, hb.x); ffma2(av[3], wv2, hb.y);
        }
#pragma unroll
        for (int p = 0; p < 4; p++) {
            float2 fq = unpack2(aq[p]);
            float2 fk = unpack2(ak[p]);
            float2 fv = unpack2(av[p]);
            int r0 = 2 * p;
            q[r0]     = siluf(fq.x) * LOG2E;
            q[r0 + 1] = siluf(fq.y) * LOG2E;
            skh[r0 * 128 + i]       = __float2half_rn(siluf(fk.x));
            skh[(r0 + 1) * 128 + i] = __float2half_rn(siluf(fk.y));
            svh[r0 * 128 + i]       = __float2half_rn(siluf(fv.x));
            svh[(r0 + 1) * 128 + i] = __float2half_rn(siluf(fv.y));
        }
    }
    __syncthreads();

    // ---- phase 3: attention 1 (fp16x2: 2 exps per MUFU, half LDS bytes) ----
    {
#pragma unroll
        for (int r = 0; r < 8; r++) {
            const __half2 qh = __float2half2_rn(q[r]);
            const uint4* kq = (const uint4*)&skh[r * 128];
            const uint4* vq = (const uint4*)&svh[r * 128];
            __half2 na[8], da[8];
#pragma unroll
            for (int p = 0; p < 8; p++) {
                na[p] = __float2half2_rn(0.f);
                da[p] = na[p];
            }
#pragma unroll
            for (int gI = 0; gI < 8; gI++) {
                uint4 kk0 = kq[2 * gI], kk1 = kq[2 * gI + 1];
                uint4 vv0 = vq[2 * gI], vv1 = vq[2 * gI + 1];
                ATTN_H16(kk0, kk1, vv0, vv1);
            }
            ATTN_EPI(num, den);
            shT[i * HSTR + r] = siluf(__fdividef(num, den));
        }
    }
    __syncthreads();

    // ---- phase 4: h2 = silu(attn1 @ W_h^T + b_h) ----
    {
        u64 a2[2];
        float bb = b_h[i2];
        a2[0] = a2[1] = pack2(bb, bb);
#pragma unroll 4
        for (int j = 0; j < 128; j++) {
            float w = g_WhT[j * 64 + i2];
            u64 w2 = pack2(w, w);
            ulonglong2 hv = *(const ulonglong2*)&shT[j * HSTR + g4 * 4];
            ffma2(a2[0], w2, hv.x);
            ffma2(a2[1], w2, hv.y);
        }
        float2 f0 = unpack2(a2[0]), f1 = unpack2(a2[1]);
        float4 o = make_float4(siluf(f0.x), siluf(f0.y),
                               siluf(f1.x), siluf(f1.y));
        *(float4*)&sh2T[i2 * HSTR + g4 * 4] = o;
    }
    __syncthreads();

    // ---- phase 5: q2,k2,v2 (64x64 GEMMs); k,v stored as half ----
    float q2r[4];
    {
        u64 aq[2], ak[2], av[2];
        float bq = Bq2[i2], bk = Bk2[i2], bv = Bv2[i2];
        aq[0] = aq[1] = pack2(bq, bq);
        ak[0] = ak[1] = pack2(bk, bk);
        av[0] = av[1] = pack2(bv, bv);
#pragma unroll 4
        for (int j = 0; j < 64; j++) {
            float wq = g_AqT2[j * 64 + i2];
            float wk = g_AkT2[j * 64 + i2];
            float wv = g_AvT2[j * 64 + i2];
            u64 wq2 = pack2(wq, wq), wk2 = pack2(wk, wk), wv2 = pack2(wv, wv);
            ulonglong2 hv = *(const ulonglong2*)&sh2T[j * HSTR + g4 * 4];
            ffma2(aq[0], wq2, hv.x); ffma2(aq[1], wq2, hv.y);
            ffma2(ak[0], wk2, hv.x); ffma2(ak[1], wk2, hv.y);
            ffma2(av[0], wv2, hv.x); ffma2(av[1], wv2, hv.y);
        }
#pragma unroll
        for (int p = 0; p < 2; p++) {
            float2 fq = unpack2(aq[p]);
            float2 fk = unpack2(ak[p]);
            float2 fv = unpack2(av[p]);
            int r0 = g4 * 4 + 2 * p;
            q2r[2 * p]     = siluf(fq.x) * LOG2E;
            q2r[2 * p + 1] = siluf(fq.y) * LOG2E;
            skh[r0 * 64 + i2]       = __float2half_rn(siluf(fk.x));
            skh[(r0 + 1) * 64 + i2] = __float2half_rn(siluf(fk.y));
            svh[r0 * 64 + i2]       = __float2half_rn(siluf(fv.x));
            svh[(r0 + 1) * 64 + i2] = __float2half_rn(siluf(fv.y));
        }
    }
    __syncthreads();

    // ---- phase 6: attention 2 (fp16x2) ----
    {
#pragma unroll
        for (int r = 0; r < 4; r++) {
            int row = g4 * 4 + r;
            const __half2 qh = __float2half2_rn(q2r[r]);
            const uint4* kq = (const uint4*)&skh[row * 64];
            const uint4* vq = (const uint4*)&svh[row * 64];
            __half2 na[8], da[8];
#pragma unroll
            for (int p = 0; p < 8; p++) {
                na[p] = __float2half2_rn(0.f);
                da[p] = na[p];
            }
#pragma unroll
            for (int gI = 0; gI < 4; gI++) {
                uint4 kk0 = kq[2 * gI], kk1 = kq[2 * gI + 1];
                uint4 vv0 = vq[2 * gI], vv1 = vq[2 * gI + 1];
                ATTN_H16(kk0, kk1, vv0, vv1);
            }
            ATTN_EPI(num, den);
            sAt2[row * 64 + i2] = siluf(__fdividef(num, den));
        }
    }
    __syncthreads();

    // ---- phase 7: y = silu(attn2 @ W_out^T + b_out) ----
    for (int idx = t; idx < RPB * 25; idx += NTHREADS) {
        int r = idx / 25;
        int o = idx - r * 25;
        float acc = b_out[o];
        const float4* wrow = (const float4*)&Wout[o * 64];
        const float4* arow = (const float4*)&sAt2[r * 64];
#pragma unroll
        for (int j = 0; j < 16; j++) {
            float4 w = wrow[j];
            float4 a = arow[j];
            acc += w.x * a.x + w.y * a.y + w.z * a.z + w.w * a.w;
        }
        sy[idx] = siluf(acc);
    }
    __syncthreads();

    // ---- phase 8: quadratic-form reduction ----
    if (t < RPB) {
        const float* y = &sy[t * 25];
        float M11 = 0.f, M12 = 0.f, M21 = 0.f, M22 = 0.f, Mpp = 0.f;
#pragma unroll
        for (int j = 0; j < 5; j++) {
            M11 += y[j] * y[j];
            M12 += y[5 + j] * y[5 + j];
            M21 += y[10 + j] * y[10 + j];
            M22 += y[15 + j] * y[15 + j];
            Mpp += y[20 + j] * y[20 + j];
        }
        float q0 = y[0], q1 = y[1], qq2 = y[2], q3 = y[3];
        float quad = M11 * (q0 * q0 + q1 * q1)
                   + (M12 + M21) * (q0 * qq2 + q1 * q3)
                   + M22 * (qq2 * qq2 + q3 * q3);
        out[row0 + t] = quad + Mpp;
    }
}

extern "C" void kernel_launch(void* const* d_in, const int* in_sizes, int n_in,
                              void* d_out, int out_size) {
    const float* x     = (const float*)d_in[0];
    const float* W_in  = (const float*)d_in[2];
    const float* b_in  = (const float*)d_in[3];
    const float* Aq4   = (const float*)d_in[4];
    const float* Bq4   = (const float*)d_in[5];
    const float* Ak4   = (const float*)d_in[6];
    const float* Bk4   = (const float*)d_in[7];
    const float* Av4   = (const float*)d_in[8];
    const float* Bv4   = (const float*)d_in[9];
    const float* W_h   = (const float*)d_in[10];
    const float* b_h   = (const float*)d_in[11];
    const float* Aq7   = (const float*)d_in[12];
    const float* Bq7   = (const float*)d_in[13];
    const float* Ak7   = (const float*)d_in[14];
    const float* Bk7   = (const float*)d_in[15];
    const float* Av7   = (const float*)d_in[16];
    const float* Bv7   = (const float*)d_in[17];
    const float* W_out = (const float*)d_in[18];
    const float* b_out = (const float*)d_in[19];

    int nrows = in_sizes[0] / 12;

    prep_weights<<<64, 256>>>(W_in, Aq4, Ak4, Av4, W_h, Aq7, Ak7, Av7);
    lemurs_fused<<<nrows / RPB, NTHREADS>>>(x, b_in, Bq4, Bk4, Bv4,
                                            b_h, Bq7, Bk7, Bv7,
                                            W_out, b_out, (float*)d_out);
}

// round 15
// speedup vs baseline: 1.4330x; 1.4330x over previous
#include <cuda_runtime.h>
#include <cuda_bf16.h>

// ---------------------------------------------------------------------------
// Fused LEMURS actor, round 15: SEPARABLE TAYLOR ATTENTION
//   num_i = sum_j e^(q_i k_j) v_j  ==>  sum_n (q_i^n/n!) * S_n,
//   S_n = sum_j k_j^n v_j  computed ONCE per row (shared across all i).
//   Degree-9 Taylor (rel err ~2e-5 for |qk|<=1.5). Attention cost drops
//   ~4x; exp/MUFU eliminated from the inner loops entirely.
//   Per row: 16 threads accumulate 20 partial sums over 8 j's each,
//   shfl_xor(16) reduce, then each thread Horner-evals 8 i's with f32x2
//   packed (num,den) coefficient pairs (9 FFMA2 per i).
// GEMM phases unchanged from the 147.9us R8 baseline.
// ---------------------------------------------------------------------------

#define RPB 8
#define NTHREADS 128
#define NPOLY 10   // coefficients 0..9 (degree 9)

typedef unsigned long long u64;

__device__ float g_WinT[12 * 128];
__device__ float g_AqT1[128 * 128];
__device__ float g_AkT1[128 * 128];
__device__ float g_AvT1[128 * 128];
__device__ float g_WhT[128 * 64];
__device__ float g_AqT2[64 * 64];
__device__ float g_AkT2[64 * 64];
__device__ float g_AvT2[64 * 64];

__device__ __forceinline__ u64 pack2(float a, float b) {
    u64 r;
    asm("mov.b64 %0, {%1, %2};" : "=l"(r) : "f"(a), "f"(b));
    return r;
}
__device__ __forceinline__ void ffma2(u64& d, u64 a, u64 b) {
    asm("fma.rn.f32x2 %0, %1, %2, %0;" : "+l"(d) : "l"(a), "l"(b));
}
__device__ __forceinline__ u64 fma2v(u64 a, u64 b, u64 c) {
    u64 d;
    asm("fma.rn.f32x2 %0, %1, %2, %3;" : "=l"(d) : "l"(a), "l"(b), "l"(c));
    return d;
}
__device__ __forceinline__ float2 unpack2(u64 v) {
    float2 f;
    asm("mov.b64 {%0, %1}, %2;" : "=f"(f.x), "=f"(f.y) : "l"(v));
    return f;
}
__device__ __forceinline__ float siluf(float v) {
    return __fdividef(v, 1.0f + __expf(-v));
}

__global__ void prep_weights(const float* __restrict__ Win,
                             const float* __restrict__ Aq1,
                             const float* __restrict__ Ak1,
                             const float* __restrict__ Av1,
                             const float* __restrict__ Wh,
                             const float* __restrict__ Aq2,
                             const float* __restrict__ Ak2,
                             const float* __restrict__ Av2) {
    int t = blockIdx.x * blockDim.x + threadIdx.x;
    int stride = gridDim.x * blockDim.x;
    for (int idx = t; idx < 128 * 12; idx += stride) {
        int i = idx / 12, j = idx - i * 12;
        g_WinT[j * 128 + i] = Win[idx];
    }
    for (int idx = t; idx < 128 * 128; idx += stride) {
        int i = idx >> 7, j = idx & 127;
        g_AqT1[j * 128 + i] = Aq1[idx];
        g_AkT1[j * 128 + i] = Ak1[idx];
        g_AvT1[j * 128 + i] = Av1[idx];
    }
    for (int idx = t; idx < 64 * 128; idx += stride) {
        int i = idx >> 7, j = idx & 127;
        g_WhT[j * 64 + i] = Wh[idx];
    }
    for (int idx = t; idx < 64 * 64; idx += stride) {
        int i = idx >> 6, j = idx & 63;
        g_AqT2[j * 64 + i] = Aq2[idx];
        g_AkT2[j * 64 + i] = Ak2[idx];
        g_AvT2[j * 64 + i] = Av2[idx];
    }
}

#define HSTR 12

// accumulate one (k, v) scalar into the 10+10 power sums
#define ACC1(kk, vv)                                                          \
    {                                                                         \
        float p = 1.f;                                                        \
        _Pragma("unroll")                                                     \
        for (int n = 0; n < NPOLY; n++) {                                     \
            Sv[n] += p * (vv);                                                \
            S1[n] += p;                                                       \
            if (n < NPOLY - 1) p *= (kk);                                     \
        }                                                                     \
    }

// shfl_xor reduce the 20 partials across the 16-thread row group
#define RED16()                                                               \
    _Pragma("unroll")                                                         \
    for (int s = 8; s > 0; s >>= 1) {                                         \
        _Pragma("unroll")                                                     \
        for (int n = 0; n < NPOLY; n++) {                                     \
            Sv[n] += __shfl_xor_sync(0xffffffffu, Sv[n], s);                  \
            S1[n] += __shfl_xor_sync(0xffffffffu, S1[n], s);                  \
        }                                                                     \
    }

// evaluate one i: Horner over packed (num,den), divide, silu
#define EVAL1(qv, dst)                                                        \
    {                                                                         \
        u64 qq = pack2((qv), (qv));                                           \
        u64 acc = an[NPOLY - 1];                                              \
        _Pragma("unroll")                                                     \
        for (int n = NPOLY - 2; n >= 0; n--) acc = fma2v(acc, qq, an[n]);     \
        float2 nd = unpack2(acc);                                             \
        (dst) = siluf(__fdividef(nd.x, nd.y));                                \
    }

__global__ __launch_bounds__(NTHREADS, 8)
void lemurs_fused(const float* __restrict__ x,
                  const float* __restrict__ b_in,
                  const float* __restrict__ Bq1, const float* __restrict__ Bk1,
                  const float* __restrict__ Bv1,
                  const float* __restrict__ b_h,
                  const float* __restrict__ Bq2, const float* __restrict__ Bk2,
                  const float* __restrict__ Bv2,
                  const float* __restrict__ Wout,
                  const float* __restrict__ b_out,
                  float* __restrict__ out) {
    __shared__ __align__(16) float sx[RPB * 12];
    __shared__ __align__(16) float shT[128 * HSTR];   // h1 -> attn1out (feat-major)
    __shared__ __align__(16) float sq[RPB * 128];     // q (raw silu)
    __shared__ __align__(16) float sk[RPB * 128];     // k
    __shared__ __align__(16) float sv[RPB * 128];     // v
    __shared__ __align__(16) float sh2T[64 * HSTR];   // h2 (feat-major)
    __shared__ __align__(16) float sAt2[RPB * 64];    // attn2 out (row-major)
    __shared__ float sy[RPB * 25];

    const int t = threadIdx.x;
    const int row0 = blockIdx.x * RPB;

    // inverse factorials 1/n!
    const float c_inv[NPOLY] = {
        1.f, 1.f, 0.5f, 1.6666667e-1f, 4.1666668e-2f, 8.3333338e-3f,
        1.3888889e-3f, 1.9841270e-4f, 2.4801588e-5f, 2.7557319e-6f};

    if (t < RPB * 12) sx[t] = x[row0 * 12 + t];
    __syncthreads();

    const int i  = t;
    const int i2 = t & 63;
    const int g4 = t >> 6;

    // ---- phase 1: h1 = silu(x @ W_in^T + b_in) -> shT feat-major ----
    {
        float acc[8];
        float bb = b_in[i];
#pragma unroll
        for (int r = 0; r < 8; r++) acc[r] = bb;
#pragma unroll
        for (int j = 0; j < 12; j++) {
            float w = g_WinT[j * 128 + i];
#pragma unroll
            for (int r = 0; r < 8; r++)
                acc[r] += w * sx[r * 12 + j];
        }
        float4 o0 = make_float4(siluf(acc[0]), siluf(acc[1]),
                                siluf(acc[2]), siluf(acc[3]));
        float4 o1 = make_float4(siluf(acc[4]), siluf(acc[5]),
                                siluf(acc[6]), siluf(acc[7]));
        *(float4*)&shT[i * HSTR]     = o0;
        *(float4*)&shT[i * HSTR + 4] = o1;
    }
    __syncthreads();

    // ---- phase 2: q1,k1,v1 (128x128 GEMMs, f32x2); raw silu to smem ----
    {
        u64 aq[4], ak[4], av[4];
        float bq = Bq1[i], bk = Bk1[i], bv = Bv1[i];
        u64 bq2 = pack2(bq, bq), bk2 = pack2(bk, bk), bv2 = pack2(bv, bv);
#pragma unroll
        for (int p = 0; p < 4; p++) { aq[p] = bq2; ak[p] = bk2; av[p] = bv2; }
#pragma unroll 4
        for (int j = 0; j < 128; j++) {
            float wq = g_AqT1[j * 128 + i];
            float wk = g_AkT1[j * 128 + i];
            float wv = g_AvT1[j * 128 + i];
            u64 wq2 = pack2(wq, wq), wk2 = pack2(wk, wk), wv2 = pack2(wv, wv);
            ulonglong2 ha = *(const ulonglong2*)&shT[j * HSTR];
            ulonglong2 hb = *(const ulonglong2*)&shT[j * HSTR + 4];
            ffma2(aq[0], wq2, ha.x); ffma2(aq[1], wq2, ha.y);
            ffma2(aq[2], wq2, hb.x); ffma2(aq[3], wq2, hb.y);
            ffma2(ak[0], wk2, ha.x); ffma2(ak[1], wk2, ha.y);
            ffma2(ak[2], wk2, hb.x); ffma2(ak[3], wk2, hb.y);
            ffma2(av[0], wv2, ha.x); ffma2(av[1], wv2, ha.y);
            ffma2(av[2], wv2, hb.x); ffma2(av[3], wv2, hb.y);
        }
#pragma unroll
        for (int p = 0; p < 4; p++) {
            float2 fq = unpack2(aq[p]);
            float2 fk = unpack2(ak[p]);
            float2 fv = unpack2(av[p]);
            int r0 = 2 * p;
            sq[r0 * 128 + i]       = siluf(fq.x);
            sq[(r0 + 1) * 128 + i] = siluf(fq.y);
            sk[r0 * 128 + i]       = siluf(fk.x);
            sk[(r0 + 1) * 128 + i] = siluf(fk.y);
            sv[r0 * 128 + i]       = siluf(fv.x);
            sv[(r0 + 1) * 128 + i] = siluf(fv.y);
        }
    }
    __syncthreads();

    // ---- phase 3: attention 1 via separable Taylor ----
    {
        const int row = t >> 4;      // 0..7
        const int js  = t & 15;      // 16 threads per row
        const int j0  = js * 8;      // this thread's 8 j's (== its 8 i's)

        float4 k0 = *(const float4*)&sk[row * 128 + j0];
        float4 k1 = *(const float4*)&sk[row * 128 + j0 + 4];
        float4 v0 = *(const float4*)&sv[row * 128 + j0];
        float4 v1 = *(const float4*)&sv[row * 128 + j0 + 4];

        float Sv[NPOLY], S1[NPOLY];
#pragma unroll
        for (int n = 0; n < NPOLY; n++) { Sv[n] = 0.f; S1[n] = 0.f; }
        ACC1(k0.x, v0.x) ACC1(k0.y, v0.y) ACC1(k0.z, v0.z) ACC1(k0.w, v0.w)
        ACC1(k1.x, v1.x) ACC1(k1.y, v1.y) ACC1(k1.z, v1.z) ACC1(k1.w, v1.w)
        RED16()

        u64 an[NPOLY];
#pragma unroll
        for (int n = 0; n < NPOLY; n++)
            an[n] = pack2(Sv[n] * c_inv[n], S1[n] * c_inv[n]);

        float4 q0 = *(const float4*)&sq[row * 128 + j0];
        float4 q1 = *(const float4*)&sq[row * 128 + j0 + 4];
        EVAL1(q0.x, shT[(j0 + 0) * HSTR + row])
        EVAL1(q0.y, shT[(j0 + 1) * HSTR + row])
        EVAL1(q0.z, shT[(j0 + 2) * HSTR + row])
        EVAL1(q0.w, shT[(j0 + 3) * HSTR + row])
        EVAL1(q1.x, shT[(j0 + 4) * HSTR + row])
        EVAL1(q1.y, shT[(j0 + 5) * HSTR + row])
        EVAL1(q1.z, shT[(j0 + 6) * HSTR + row])
        EVAL1(q1.w, shT[(j0 + 7) * HSTR + row])
    }
    __syncthreads();

    // ---- phase 4: h2 = silu(attn1 @ W_h^T + b_h) -> sh2T feat-major ----
    {
        u64 a2[2];
        float bb = b_h[i2];
        a2[0] = a2[1] = pack2(bb, bb);
#pragma unroll 4
        for (int j = 0; j < 128; j++) {
            float w = g_WhT[j * 64 + i2];
            u64 w2 = pack2(w, w);
            ulonglong2 hv = *(const ulonglong2*)&shT[j * HSTR + g4 * 4];
            ffma2(a2[0], w2, hv.x);
            ffma2(a2[1], w2, hv.y);
        }
        float2 f0 = unpack2(a2[0]), f1 = unpack2(a2[1]);
        float4 o = make_float4(siluf(f0.x), siluf(f0.y),
                               siluf(f1.x), siluf(f1.y));
        *(float4*)&sh2T[i2 * HSTR + g4 * 4] = o;
    }
    __syncthreads();

    // ---- phase 5: q2,k2,v2 (64x64 GEMMs); raw silu to smem ----
    {
        u64 aq[2], ak[2], av[2];
        float bq = Bq2[i2], bk = Bk2[i2], bv = Bv2[i2];
        aq[0] = aq[1] = pack2(bq, bq);
        ak[0] = ak[1] = pack2(bk, bk);
        av[0] = av[1] = pack2(bv, bv);
#pragma unroll 4
        for (int j = 0; j < 64; j++) {
            float wq = g_AqT2[j * 64 + i2];
            float wk = g_AkT2[j * 64 + i2];
            float wv = g_AvT2[j * 64 + i2];
            u64 wq2 = pack2(wq, wq), wk2 = pack2(wk, wk), wv2 = pack2(wv, wv);
            ulonglong2 hv = *(const ulonglong2*)&sh2T[j * HSTR + g4 * 4];
            ffma2(aq[0], wq2, hv.x); ffma2(aq[1], wq2, hv.y);
            ffma2(ak[0], wk2, hv.x); ffma2(ak[1], wk2, hv.y);
            ffma2(av[0], wv2, hv.x); ffma2(av[1], wv2, hv.y);
        }
#pragma unroll
        for (int p = 0; p < 2; p++) {
            float2 fq = unpack2(aq[p]);
            float2 fk = unpack2(ak[p]);
            float2 fv = unpack2(av[p]);
            int r0 = g4 * 4 + 2 * p;
            sq[r0 * 64 + i2]       = siluf(fq.x);
            sq[(r0 + 1) * 64 + i2] = siluf(fq.y);
            sk[r0 * 64 + i2]       = siluf(fk.x);
            sk[(r0 + 1) * 64 + i2] = siluf(fk.y);
            sv[r0 * 64 + i2]       = siluf(fv.x);
            sv[(r0 + 1) * 64 + i2] = siluf(fv.y);
        }
    }
    __syncthreads();

    // ---- phase 6: attention 2 via separable Taylor (64-dim) ----
    {
        const int row = t >> 4;
        const int js  = t & 15;
        const int j0  = js * 4;      // 4 j's / 4 i's per thread

        float4 kk = *(const float4*)&sk[row * 64 + j0];
        float4 vv = *(const float4*)&sv[row * 64 + j0];

        float Sv[NPOLY], S1[NPOLY];
#pragma unroll
        for (int n = 0; n < NPOLY; n++) { Sv[n] = 0.f; S1[n] = 0.f; }
        ACC1(kk.x, vv.x) ACC1(kk.y, vv.y) ACC1(kk.z, vv.z) ACC1(kk.w, vv.w)
        RED16()

        u64 an[NPOLY];
#pragma unroll
        for (int n = 0; n < NPOLY; n++)
            an[n] = pack2(Sv[n] * c_inv[n], S1[n] * c_inv[n]);

        float4 qv = *(const float4*)&sq[row * 64 + j0];
        EVAL1(qv.x, sAt2[row * 64 + j0 + 0])
        EVAL1(qv.y, sAt2[row * 64 + j0 + 1])
        EVAL1(qv.z, sAt2[row * 64 + j0 + 2])
        EVAL1(qv.w, sAt2[row * 64 + j0 + 3])
    }
    __syncthreads();

    // ---- phase 7: y = silu(attn2 @ W_out^T + b_out) ----
    for (int idx = t; idx < RPB * 25; idx += NTHREADS) {
        int r = idx / 25;
        int o = idx - r * 25;
        float acc = b_out[o];
        const float4* wrow = (const float4*)&Wout[o * 64];
        const float4* arow = (const float4*)&sAt2[r * 64];
#pragma unroll
        for (int j = 0; j < 16; j++) {
            float4 w = wrow[j];
            float4 a = arow[j];
            acc += w.x * a.x + w.y * a.y + w.z * a.z + w.w * a.w;
        }
        sy[idx] = siluf(acc);
    }
    __syncthreads();

    // ---- phase 8: quadratic-form reduction ----
    if (t < RPB) {
        const float* y = &sy[t * 25];
        float M11 = 0.f, M12 = 0.f, M21 = 0.f, M22 = 0.f, Mpp = 0.f;
#pragma unroll
        for (int j = 0; j < 5; j++) {
            M11 += y[j] * y[j];
            M12 += y[5 + j] * y[5 + j];
            M21 += y[10 + j] * y[10 + j];
            M22 += y[15 + j] * y[15 + j];
            Mpp += y[20 + j] * y[20 + j];
        }
        float q0 = y[0], q1 = y[1], qq2 = y[2], q3 = y[3];
        float quad = M11 * (q0 * q0 + q1 * q1)
                   + (M12 + M21) * (q0 * qq2 + q1 * q3)
                   + M22 * (qq2 * qq2 + q3 * q3);
        out[row0 + t] = quad + Mpp;
    }
}

extern "C" void kernel_launch(void* const* d_in, const int* in_sizes, int n_in,
                              void* d_out, int out_size) {
    const float* x     = (const float*)d_in[0];
    const float* W_in  = (const float*)d_in[2];
    const float* b_in  = (const float*)d_in[3];
    const float* Aq4   = (const float*)d_in[4];
    const float* Bq4   = (const float*)d_in[5];
    const float* Ak4   = (const float*)d_in[6];
    const float* Bk4   = (const float*)d_in[7];
    const float* Av4   = (const float*)d_in[8];
    const float* Bv4   = (const float*)d_in[9];
    const float* W_h   = (const float*)d_in[10];
    const float* b_h   = (const float*)d_in[11];
    const float* Aq7   = (const float*)d_in[12];
    const float* Bq7   = (const float*)d_in[13];
    const float* Ak7   = (const float*)d_in[14];
    const float* Bk7   = (const float*)d_in[15];
    const float* Av7   = (const float*)d_in[16];
    const float* Bv7   = (const float*)d_in[17];
    const float* W_out = (const float*)d_in[18];
    const float* b_out = (const float*)d_in[19];

    int nrows = in_sizes[0] / 12;

    prep_weights<<<64, 256>>>(W_in, Aq4, Ak4, Av4, W_h, Aq7, Ak7, Av7);
    lemurs_fused<<<nrows / RPB, NTHREADS>>>(x, b_in, Bq4, Bk4, Bv4,
                                            b_h, Bq7, Bk7, Bv7,
                                            W_out, b_out, (float*)d_out);
}

// round 16
// speedup vs baseline: 1.5948x; 1.1129x over previous
#include <cuda_runtime.h>
#include <cuda_bf16.h>

// ---------------------------------------------------------------------------
// Fused LEMURS actor, round 16: R15 (separable Taylor attention) +
// bf16-compressed packed weights.
//   - (wq,wk,wv) packed bf16 in one uint2 -> ONE LDG.64 per j (was 3 LDG.32)
//   - weight footprint 278KB -> ~145KB: fits L1 -> weight loads become L1 hits
//   - bf16 -> duplicated-f32x2 operand via PRMT (alu pipe) + MOV.64
// Attention and phase structure unchanged from the 114.8us R15.
// ---------------------------------------------------------------------------

#define RPB 8
#define NTHREADS 128
#define NPOLY 10

typedef unsigned long long u64;

__device__ float  g_WinT[12 * 128];
__device__ uint2  g_Wqkv1[128 * 128];    // [j*128+i] = {bf(wq)|bf(wk)<<16, bf(wv)}
__device__ unsigned short g_Whb[128 * 64];  // bf16(W_h^T)
__device__ uint2  g_Wqkv2[64 * 64];
__device__ float  g_WoutT[25 * 64];      // unchanged layout copy (f32, tiny)

__device__ __forceinline__ u64 pack2(float a, float b) {
    u64 r;
    asm("mov.b64 %0, {%1, %2};" : "=l"(r) : "f"(a), "f"(b));
    return r;
}
__device__ __forceinline__ void ffma2(u64& d, u64 a, u64 b) {
    asm("fma.rn.f32x2 %0, %1, %2, %0;" : "+l"(d) : "l"(a), "l"(b));
}
__device__ __forceinline__ u64 fma2v(u64 a, u64 b, u64 c) {
    u64 d;
    asm("fma.rn.f32x2 %0, %1, %2, %3;" : "=l"(d) : "l"(a), "l"(b), "l"(c));
    return d;
}
__device__ __forceinline__ float2 unpack2(u64 v) {
    float2 f;
    asm("mov.b64 {%0, %1}, %2;" : "=f"(f.x), "=f"(f.y) : "l"(v));
    return f;
}
__device__ __forceinline__ float siluf(float v) {
    return __fdividef(v, 1.0f + __expf(-v));
}
// bf16 (low/high half of u32) -> (f32,f32) duplicated pair
__device__ __forceinline__ u64 bfdup_lo(unsigned w) {
    u64 d;
    asm("{.reg .b32 t; prmt.b32 t, %1, 0, 0x1044; mov.b64 %0, {t, t};}"
        : "=l"(d) : "r"(w));
    return d;
}
__device__ __forceinline__ u64 bfdup_hi(unsigned w) {
    u64 d;
    asm("{.reg .b32 t; prmt.b32 t, %1, 0, 0x3244; mov.b64 %0, {t, t};}"
        : "=l"(d) : "r"(w));
    return d;
}

__device__ __forceinline__ unsigned short f2bf(float f) {
    __nv_bfloat16 b = __float2bfloat16(f);
    return *reinterpret_cast<unsigned short*>(&b);
}

__global__ void prep_weights(const float* __restrict__ Win,
                             const float* __restrict__ Aq1,
                             const float* __restrict__ Ak1,
                             const float* __restrict__ Av1,
                             const float* __restrict__ Wh,
                             const float* __restrict__ Aq2,
                             const float* __restrict__ Ak2,
                             const float* __restrict__ Av2,
                             const float* __restrict__ Wout) {
    int t = blockIdx.x * blockDim.x + threadIdx.x;
    int stride = gridDim.x * blockDim.x;
    for (int idx = t; idx < 128 * 12; idx += stride) {
        int i = idx / 12, j = idx - i * 12;
        g_WinT[j * 128 + i] = Win[idx];
    }
    for (int idx = t; idx < 128 * 128; idx += stride) {
        int i = idx >> 7, j = idx & 127;
        unsigned q = f2bf(Aq1[idx]);
        unsigned k = f2bf(Ak1[idx]);
        unsigned v = f2bf(Av1[idx]);
        g_Wqkv1[j * 128 + i] = make_uint2(q | (k << 16), v);
    }
    for (int idx = t; idx < 64 * 128; idx += stride) {
        int i = idx >> 7, j = idx & 127;
        g_Whb[j * 64 + i] = f2bf(Wh[idx]);
    }
    for (int idx = t; idx < 64 * 64; idx += stride) {
        int i = idx >> 6, j = idx & 63;
        unsigned q = f2bf(Aq2[idx]);
        unsigned k = f2bf(Ak2[idx]);
        unsigned v = f2bf(Av2[idx]);
        g_Wqkv2[j * 64 + i] = make_uint2(q | (k << 16), v);
    }
    for (int idx = t; idx < 25 * 64; idx += stride)
        g_WoutT[idx] = Wout[idx];
}

#define HSTR 12

#define ACC1(kk, vv)                                                          \
    {                                                                         \
        float p = 1.f;                                                        \
        _Pragma("unroll")                                                     \
        for (int n = 0; n < NPOLY; n++) {                                     \
            Sv[n] += p * (vv);                                                \
            S1[n] += p;                                                       \
            if (n < NPOLY - 1) p *= (kk);                                     \
        }                                                                     \
    }

#define RED16()                                                               \
    _Pragma("unroll")                                                         \
    for (int s = 8; s > 0; s >>= 1) {                                         \
        _Pragma("unroll")                                                     \
        for (int n = 0; n < NPOLY; n++) {                                     \
            Sv[n] += __shfl_xor_sync(0xffffffffu, Sv[n], s);                  \
            S1[n] += __shfl_xor_sync(0xffffffffu, S1[n], s);                  \
        }                                                                     \
    }

#define EVAL1(qv, dst)                                                        \
    {                                                                         \
        u64 qq = pack2((qv), (qv));                                           \
        u64 acc = an[NPOLY - 1];                                              \
        _Pragma("unroll")                                                     \
        for (int n = NPOLY - 2; n >= 0; n--) acc = fma2v(acc, qq, an[n]);     \
        float2 nd = unpack2(acc);                                             \
        (dst) = siluf(__fdividef(nd.x, nd.y));                                \
    }

__global__ __launch_bounds__(NTHREADS, 8)
void lemurs_fused(const float* __restrict__ x,
                  const float* __restrict__ b_in,
                  const float* __restrict__ Bq1, const float* __restrict__ Bk1,
                  const float* __restrict__ Bv1,
                  const float* __restrict__ b_h,
                  const float* __restrict__ Bq2, const float* __restrict__ Bk2,
                  const float* __restrict__ Bv2,
                  const float* __restrict__ b_out,
                  float* __restrict__ out) {
    __shared__ __align__(16) float sx[RPB * 12];
    __shared__ __align__(16) float shT[128 * HSTR];   // h1 -> attn1out (feat-major)
    __shared__ __align__(16) float sq[RPB * 128];
    __shared__ __align__(16) float sk[RPB * 128];
    __shared__ __align__(16) float sv[RPB * 128];
    __shared__ __align__(16) float sh2T[64 * HSTR];
    __shared__ __align__(16) float sAt2[RPB * 64];
    __shared__ float sy[RPB * 25];

    const int t = threadIdx.x;
    const int row0 = blockIdx.x * RPB;

    const float c_inv[NPOLY] = {
        1.f, 1.f, 0.5f, 1.6666667e-1f, 4.1666668e-2f, 8.3333338e-3f,
        1.3888889e-3f, 1.9841270e-4f, 2.4801588e-5f, 2.7557319e-6f};

    if (t < RPB * 12) sx[t] = x[row0 * 12 + t];
    __syncthreads();

    const int i  = t;
    const int i2 = t & 63;
    const int g4 = t >> 6;

    // ---- phase 1: h1 = silu(x @ W_in^T + b_in) -> shT feat-major ----
    {
        float acc[8];
        float bb = b_in[i];
#pragma unroll
        for (int r = 0; r < 8; r++) acc[r] = bb;
#pragma unroll
        for (int j = 0; j < 12; j++) {
            float w = g_WinT[j * 128 + i];
#pragma unroll
            for (int r = 0; r < 8; r++)
                acc[r] += w * sx[r * 12 + j];
        }
        float4 o0 = make_float4(siluf(acc[0]), siluf(acc[1]),
                                siluf(acc[2]), siluf(acc[3]));
        float4 o1 = make_float4(siluf(acc[4]), siluf(acc[5]),
                                siluf(acc[6]), siluf(acc[7]));
        *(float4*)&shT[i * HSTR]     = o0;
        *(float4*)&shT[i * HSTR + 4] = o1;
    }
    __syncthreads();

    // ---- phase 2: q1,k1,v1 (128x128 GEMMs); bf16 packed weights ----
    {
        u64 aq[4], ak[4], av[4];
        float bq = Bq1[i], bk = Bk1[i], bv = Bv1[i];
        u64 bq2 = pack2(bq, bq), bk2 = pack2(bk, bk), bv2 = pack2(bv, bv);
#pragma unroll
        for (int p = 0; p < 4; p++) { aq[p] = bq2; ak[p] = bk2; av[p] = bv2; }
#pragma unroll 4
        for (int j = 0; j < 128; j++) {
            uint2 wp = g_Wqkv1[j * 128 + i];
            u64 wq2 = bfdup_lo(wp.x);
            u64 wk2 = bfdup_hi(wp.x);
            u64 wv2 = bfdup_lo(wp.y);
            ulonglong2 ha = *(const ulonglong2*)&shT[j * HSTR];
            ulonglong2 hb = *(const ulonglong2*)&shT[j * HSTR + 4];
            ffma2(aq[0], wq2, ha.x); ffma2(aq[1], wq2, ha.y);
            ffma2(aq[2], wq2, hb.x); ffma2(aq[3], wq2, hb.y);
            ffma2(ak[0], wk2, ha.x); ffma2(ak[1], wk2, ha.y);
            ffma2(ak[2], wk2, hb.x); ffma2(ak[3], wk2, hb.y);
            ffma2(av[0], wv2, ha.x); ffma2(av[1], wv2, ha.y);
            ffma2(av[2], wv2, hb.x); ffma2(av[3], wv2, hb.y);
        }
#pragma unroll
        for (int p = 0; p < 4; p++) {
            float2 fq = unpack2(aq[p]);
            float2 fk = unpack2(ak[p]);
            float2 fv = unpack2(av[p]);
            int r0 = 2 * p;
            sq[r0 * 128 + i]       = siluf(fq.x);
            sq[(r0 + 1) * 128 + i] = siluf(fq.y);
            sk[r0 * 128 + i]       = siluf(fk.x);
            sk[(r0 + 1) * 128 + i] = siluf(fk.y);
            sv[r0 * 128 + i]       = siluf(fv.x);
            sv[(r0 + 1) * 128 + i] = siluf(fv.y);
        }
    }
    __syncthreads();

    // ---- phase 3: attention 1 via separable Taylor ----
    {
        const int row = t >> 4;
        const int js  = t & 15;
        const int j0  = js * 8;

        float4 k0 = *(const float4*)&sk[row * 128 + j0];
        float4 k1 = *(const float4*)&sk[row * 128 + j0 + 4];
        float4 v0 = *(const float4*)&sv[row * 128 + j0];
        float4 v1 = *(const float4*)&sv[row * 128 + j0 + 4];

        float Sv[NPOLY], S1[NPOLY];
#pragma unroll
        for (int n = 0; n < NPOLY; n++) { Sv[n] = 0.f; S1[n] = 0.f; }
        ACC1(k0.x, v0.x) ACC1(k0.y, v0.y) ACC1(k0.z, v0.z) ACC1(k0.w, v0.w)
        ACC1(k1.x, v1.x) ACC1(k1.y, v1.y) ACC1(k1.z, v1.z) ACC1(k1.w, v1.w)
        RED16()

        u64 an[NPOLY];
#pragma unroll
        for (int n = 0; n < NPOLY; n++)
            an[n] = pack2(Sv[n] * c_inv[n], S1[n] * c_inv[n]);

        float4 q0 = *(const float4*)&sq[row * 128 + j0];
        float4 q1 = *(const float4*)&sq[row * 128 + j0 + 4];
        EVAL1(q0.x, shT[(j0 + 0) * HSTR + row])
        EVAL1(q0.y, shT[(j0 + 1) * HSTR + row])
        EVAL1(q0.z, shT[(j0 + 2) * HSTR + row])
        EVAL1(q0.w, shT[(j0 + 3) * HSTR + row])
        EVAL1(q1.x, shT[(j0 + 4) * HSTR + row])
        EVAL1(q1.y, shT[(j0 + 5) * HSTR + row])
        EVAL1(q1.z, shT[(j0 + 6) * HSTR + row])
        EVAL1(q1.w, shT[(j0 + 7) * HSTR + row])
    }
    __syncthreads();

    // ---- phase 4: h2 = silu(attn1 @ W_h^T + b_h); bf16 weights ----
    {
        u64 a2[2];
        float bb = b_h[i2];
        a2[0] = a2[1] = pack2(bb, bb);
#pragma unroll 4
        for (int j = 0; j < 128; j++) {
            unsigned w = g_Whb[j * 64 + i2];
            u64 w2 = bfdup_lo(w);
            ulonglong2 hv = *(const ulonglong2*)&shT[j * HSTR + g4 * 4];
            ffma2(a2[0], w2, hv.x);
            ffma2(a2[1], w2, hv.y);
        }
        float2 f0 = unpack2(a2[0]), f1 = unpack2(a2[1]);
        float4 o = make_float4(siluf(f0.x), siluf(f0.y),
                               siluf(f1.x), siluf(f1.y));
        *(float4*)&sh2T[i2 * HSTR + g4 * 4] = o;
    }
    __syncthreads();

    // ---- phase 5: q2,k2,v2 (64x64 GEMMs); bf16 packed weights ----
    {
        u64 aq[2], ak[2], av[2];
        float bq = Bq2[i2], bk = Bk2[i2], bv = Bv2[i2];
        aq[0] = aq[1] = pack2(bq, bq);
        ak[0] = ak[1] = pack2(bk, bk);
        av[0] = av[1] = pack2(bv, bv);
#pragma unroll 4
        for (int j = 0; j < 64; j++) {
            uint2 wp = g_Wqkv2[j * 64 + i2];
            u64 wq2 = bfdup_lo(wp.x);
            u64 wk2 = bfdup_hi(wp.x);
            u64 wv2 = bfdup_lo(wp.y);
            ulonglong2 hv = *(const ulonglong2*)&sh2T[j * HSTR + g4 * 4];
            ffma2(aq[0], wq2, hv.x); ffma2(aq[1], wq2, hv.y);
            ffma2(ak[0], wk2, hv.x); ffma2(ak[1], wk2, hv.y);
            ffma2(av[0], wv2, hv.x); ffma2(av[1], wv2, hv.y);
        }
#pragma unroll
        for (int p = 0; p < 2; p++) {
            float2 fq = unpack2(aq[p]);
            float2 fk = unpack2(ak[p]);
            float2 fv = unpack2(av[p]);
            int r0 = g4 * 4 + 2 * p;
            sq[r0 * 64 + i2]       = siluf(fq.x);
            sq[(r0 + 1) * 64 + i2] = siluf(fq.y);
            sk[r0 * 64 + i2]       = siluf(fk.x);
            sk[(r0 + 1) * 64 + i2] = siluf(fk.y);
            sv[r0 * 64 + i2]       = siluf(fv.x);
            sv[(r0 + 1) * 64 + i2] = siluf(fv.y);
        }
    }
    __syncthreads();

    // ---- phase 6: attention 2 via separable Taylor (64-dim) ----
    {
        const int row = t >> 4;
        const int js  = t & 15;
        const int j0  = js * 4;

        float4 kk = *(const float4*)&sk[row * 64 + j0];
        float4 vv = *(const float4*)&sv[row * 64 + j0];

        float Sv[NPOLY], S1[NPOLY];
#pragma unroll
        for (int n = 0; n < NPOLY; n++) { Sv[n] = 0.f; S1[n] = 0.f; }
        ACC1(kk.x, vv.x) ACC1(kk.y, vv.y) ACC1(kk.z, vv.z) ACC1(kk.w, vv.w)
        RED16()

        u64 an[NPOLY];
#pragma unroll
        for (int n = 0; n < NPOLY; n++)
            an[n] = pack2(Sv[n] * c_inv[n], S1[n] * c_inv[n]);

        float4 qv = *(const float4*)&sq[row * 64 + j0];
        EVAL1(qv.x, sAt2[row * 64 + j0 + 0])
        EVAL1(qv.y, sAt2[row * 64 + j0 + 1])
        EVAL1(qv.z, sAt2[row * 64 + j0 + 2])
        EVAL1(qv.w, sAt2[row * 64 + j0 + 3])
    }
    __syncthreads();

    // ---- phase 7: y = silu(attn2 @ W_out^T + b_out) ----
    for (int idx = t; idx < RPB * 25; idx += NTHREADS) {
        int r = idx / 25;
        int o = idx - r * 25;
        float acc = b_out[o];
        const float4* wrow = (const float4*)&g_WoutT[o * 64];
        const float4* arow = (const float4*)&sAt2[r * 64];
#pragma unroll
        for (int j = 0; j < 16; j++) {
            float4 w = wrow[j];
            float4 a = arow[j];
            acc += w.x * a.x + w.y * a.y + w.z * a.z + w.w * a.w;
        }
        sy[idx] = siluf(acc);
    }
    __syncthreads();

    // ---- phase 8: quadratic-form reduction ----
    if (t < RPB) {
        const float* y = &sy[t * 25];
        float M11 = 0.f, M12 = 0.f, M21 = 0.f, M22 = 0.f, Mpp = 0.f;
#pragma unroll
        for (int j = 0; j < 5; j++) {
            M11 += y[j] * y[j];
            M12 += y[5 + j] * y[5 + j];
            M21 += y[10 + j] * y[10 + j];
            M22 += y[15 + j] * y[15 + j];
            Mpp += y[20 + j] * y[20 + j];
        }
        float q0 = y[0], q1 = y[1], qq2 = y[2], q3 = y[3];
        float quad = M11 * (q0 * q0 + q1 * q1)
                   + (M12 + M21) * (q0 * qq2 + q1 * q3)
                   + M22 * (qq2 * qq2 + q3 * q3);
        out[row0 + t] = quad + Mpp;
    }
}

extern "C" void kernel_launch(void* const* d_in, const int* in_sizes, int n_in,
                              void* d_out, int out_size) {
    const float* x     = (const float*)d_in[0];
    const float* W_in  = (const float*)d_in[2];
    const float* b_in  = (const float*)d_in[3];
    const float* Aq4   = (const float*)d_in[4];
    const float* Bq4   = (const float*)d_in[5];
    const float* Ak4   = (const float*)d_in[6];
    const float* Bk4   = (const float*)d_in[7];
    const float* Av4   = (const float*)d_in[8];
    const float* Bv4   = (const float*)d_in[9];
    const float* W_h   = (const float*)d_in[10];
    const float* b_h   = (const float*)d_in[11];
    const float* Aq7   = (const float*)d_in[12];
    const float* Bq7   = (const float*)d_in[13];
    const float* Ak7   = (const float*)d_in[14];
    const float* Bk7   = (const float*)d_in[15];
    const float* Av7   = (const float*)d_in[16];
    const float* Bv7   = (const float*)d_in[17];
    const float* W_out = (const float*)d_in[18];
    const float* b_out = (const float*)d_in[19];

    int nrows = in_sizes[0] / 12;

    prep_weights<<<64, 256>>>(W_in, Aq4, Ak4, Av4, W_h, Aq7, Ak7, Av7, W_out);
    lemurs_fused<<<nrows / RPB, NTHREADS>>>(x, b_in, Bq4, Bk4, Bv4,
                                            b_h, Bq7, Bk7, Bv7,
                                            b_out, (float*)d_out);
}

// round 17
// speedup vs baseline: 1.6286x; 1.0212x over previous
#include <cuda_runtime.h>
#include <cuda_bf16.h>

// ---------------------------------------------------------------------------
// Fused LEMURS actor, round 17: R16 + attention bank-conflict fix + f32x2
// power chains.
//   - stride-16 i-mapping in attention (i = js + 16u): conflict-free LDS.32
//     loads, ~2-way stores (was 16-way STS conflicts = ~128 wf/warp)
//   - ACC accumulates packed (v*k^n, k^n) with mul2/add2: 19 instr/elem
//   - NPOLY 9 (degree-8 Taylor; worst-case |qk|~1.3 -> err ~3e-5)
// GEMM phases + bf16 packed weights unchanged from the 103.1us R16.
// ---------------------------------------------------------------------------

#define RPB 8
#define NTHREADS 128
#define NPOLY 9

typedef unsigned long long u64;

__device__ float  g_WinT[12 * 128];
__device__ uint2  g_Wqkv1[128 * 128];    // {bf(wq)|bf(wk)<<16, bf(wv)}
__device__ unsigned short g_Whb[128 * 64];
__device__ uint2  g_Wqkv2[64 * 64];
__device__ float  g_WoutT[25 * 64];

__device__ __forceinline__ u64 pack2(float a, float b) {
    u64 r;
    asm("mov.b64 %0, {%1, %2};" : "=l"(r) : "f"(a), "f"(b));
    return r;
}
__device__ __forceinline__ void ffma2(u64& d, u64 a, u64 b) {
    asm("fma.rn.f32x2 %0, %1, %2, %0;" : "+l"(d) : "l"(a), "l"(b));
}
__device__ __forceinline__ u64 fma2v(u64 a, u64 b, u64 c) {
    u64 d;
    asm("fma.rn.f32x2 %0, %1, %2, %3;" : "=l"(d) : "l"(a), "l"(b), "l"(c));
    return d;
}
__device__ __forceinline__ u64 mul2(u64 a, u64 b) {
    u64 d;
    asm("mul.rn.f32x2 %0, %1, %2;" : "=l"(d) : "l"(a), "l"(b));
    return d;
}
__device__ __forceinline__ u64 add2(u64 a, u64 b) {
    u64 d;
    asm("add.rn.f32x2 %0, %1, %2;" : "=l"(d) : "l"(a), "l"(b));
    return d;
}
__device__ __forceinline__ float2 unpack2(u64 v) {
    float2 f;
    asm("mov.b64 {%0, %1}, %2;" : "=f"(f.x), "=f"(f.y) : "l"(v));
    return f;
}
__device__ __forceinline__ float siluf(float v) {
    return __fdividef(v, 1.0f + __expf(-v));
}
__device__ __forceinline__ u64 bfdup_lo(unsigned w) {
    u64 d;
    asm("{.reg .b32 t; prmt.b32 t, %1, 0, 0x1044; mov.b64 %0, {t, t};}"
        : "=l"(d) : "r"(w));
    return d;
}
__device__ __forceinline__ u64 bfdup_hi(unsigned w) {
    u64 d;
    asm("{.reg .b32 t; prmt.b32 t, %1, 0, 0x3244; mov.b64 %0, {t, t};}"
        : "=l"(d) : "r"(w));
    return d;
}

__device__ __forceinline__ unsigned short f2bf(float f) {
    __nv_bfloat16 b = __float2bfloat16(f);
    return *reinterpret_cast<unsigned short*>(&b);
}

__global__ void prep_weights(const float* __restrict__ Win,
                             const float* __restrict__ Aq1,
                             const float* __restrict__ Ak1,
                             const float* __restrict__ Av1,
                             const float* __restrict__ Wh,
                             const float* __restrict__ Aq2,
                             const float* __restrict__ Ak2,
                             const float* __restrict__ Av2,
                             const float* __restrict__ Wout) {
    int t = blockIdx.x * blockDim.x + threadIdx.x;
    int stride = gridDim.x * blockDim.x;
    for (int idx = t; idx < 128 * 12; idx += stride) {
        int i = idx / 12, j = idx - i * 12;
        g_WinT[j * 128 + i] = Win[idx];
    }
    for (int idx = t; idx < 128 * 128; idx += stride) {
        int i = idx >> 7, j = idx & 127;
        unsigned q = f2bf(Aq1[idx]);
        unsigned k = f2bf(Ak1[idx]);
        unsigned v = f2bf(Av1[idx]);
        g_Wqkv1[j * 128 + i] = make_uint2(q | (k << 16), v);
    }
    for (int idx = t; idx < 64 * 128; idx += stride) {
        int i = idx >> 7, j = idx & 127;
        g_Whb[j * 64 + i] = f2bf(Wh[idx]);
    }
    for (int idx = t; idx < 64 * 64; idx += stride) {
        int i = idx >> 6, j = idx & 63;
        unsigned q = f2bf(Aq2[idx]);
        unsigned k = f2bf(Ak2[idx]);
        unsigned v = f2bf(Av2[idx]);
        g_Wqkv2[j * 64 + i] = make_uint2(q | (k << 16), v);
    }
    for (int idx = t; idx < 25 * 64; idx += stride)
        g_WoutT[idx] = Wout[idx];
}

#define HSTR 12

// evaluate one i: Horner over packed (num,den), divide, silu
#define EVAL1(qv, dst)                                                        \
    {                                                                         \
        u64 qq = pack2((qv), (qv));                                           \
        u64 acc = an[NPOLY - 1];                                              \
        _Pragma("unroll")                                                     \
        for (int n = NPOLY - 2; n >= 0; n--) acc = fma2v(acc, qq, an[n]);     \
        float2 nd = unpack2(acc);                                             \
        (dst) = siluf(__fdividef(nd.x, nd.y));                                \
    }

__global__ __launch_bounds__(NTHREADS, 8)
void lemurs_fused(const float* __restrict__ x,
                  const float* __restrict__ b_in,
                  const float* __restrict__ Bq1, const float* __restrict__ Bk1,
                  const float* __restrict__ Bv1,
                  const float* __restrict__ b_h,
                  const float* __restrict__ Bq2, const float* __restrict__ Bk2,
                  const float* __restrict__ Bv2,
                  const float* __restrict__ b_out,
                  float* __restrict__ out) {
    __shared__ __align__(16) float sx[RPB * 12];
    __shared__ __align__(16) float shT[128 * HSTR];   // h1 -> attn1out (feat-major)
    __shared__ __align__(16) float sq[RPB * 128];
    __shared__ __align__(16) float sk[RPB * 128];
    __shared__ __align__(16) float sv[RPB * 128];
    __shared__ __align__(16) float sh2T[64 * HSTR];
    __shared__ __align__(16) float sAt2[RPB * 64];
    __shared__ float sy[RPB * 25];

    const int t = threadIdx.x;
    const int row0 = blockIdx.x * RPB;

    const float c_inv[NPOLY] = {
        1.f, 1.f, 0.5f, 1.6666667e-1f, 4.1666668e-2f, 8.3333338e-3f,
        1.3888889e-3f, 1.9841270e-4f, 2.4801588e-5f};

    if (t < RPB * 12) sx[t] = x[row0 * 12 + t];
    __syncthreads();

    const int i  = t;
    const int i2 = t & 63;
    const int g4 = t >> 6;

    // ---- phase 1: h1 = silu(x @ W_in^T + b_in) -> shT feat-major ----
    {
        float acc[8];
        float bb = b_in[i];
#pragma unroll
        for (int r = 0; r < 8; r++) acc[r] = bb;
#pragma unroll
        for (int j = 0; j < 12; j++) {
            float w = g_WinT[j * 128 + i];
#pragma unroll
            for (int r = 0; r < 8; r++)
                acc[r] += w * sx[r * 12 + j];
        }
        float4 o0 = make_float4(siluf(acc[0]), siluf(acc[1]),
                                siluf(acc[2]), siluf(acc[3]));
        float4 o1 = make_float4(siluf(acc[4]), siluf(acc[5]),
                                siluf(acc[6]), siluf(acc[7]));
        *(float4*)&shT[i * HSTR]     = o0;
        *(float4*)&shT[i * HSTR + 4] = o1;
    }
    __syncthreads();

    // ---- phase 2: q1,k1,v1 (128x128 GEMMs); bf16 packed weights ----
    {
        u64 aq[4], ak[4], av[4];
        float bq = Bq1[i], bk = Bk1[i], bv = Bv1[i];
        u64 bq2 = pack2(bq, bq), bk2 = pack2(bk, bk), bv2 = pack2(bv, bv);
#pragma unroll
        for (int p = 0; p < 4; p++) { aq[p] = bq2; ak[p] = bk2; av[p] = bv2; }
#pragma unroll 4
        for (int j = 0; j < 128; j++) {
            uint2 wp = g_Wqkv1[j * 128 + i];
            u64 wq2 = bfdup_lo(wp.x);
            u64 wk2 = bfdup_hi(wp.x);
            u64 wv2 = bfdup_lo(wp.y);
            ulonglong2 ha = *(const ulonglong2*)&shT[j * HSTR];
            ulonglong2 hb = *(const ulonglong2*)&shT[j * HSTR + 4];
            ffma2(aq[0], wq2, ha.x); ffma2(aq[1], wq2, ha.y);
            ffma2(aq[2], wq2, hb.x); ffma2(aq[3], wq2, hb.y);
            ffma2(ak[0], wk2, ha.x); ffma2(ak[1], wk2, ha.y);
            ffma2(ak[2], wk2, hb.x); ffma2(ak[3], wk2, hb.y);
            ffma2(av[0], wv2, ha.x); ffma2(av[1], wv2, ha.y);
            ffma2(av[2], wv2, hb.x); ffma2(av[3], wv2, hb.y);
        }
#pragma unroll
        for (int p = 0; p < 4; p++) {
            float2 fq = unpack2(aq[p]);
            float2 fk = unpack2(ak[p]);
            float2 fv = unpack2(av[p]);
            int r0 = 2 * p;
            sq[r0 * 128 + i]       = siluf(fq.x);
            sq[(r0 + 1) * 128 + i] = siluf(fq.y);
            sk[r0 * 128 + i]       = siluf(fk.x);
            sk[(r0 + 1) * 128 + i] = siluf(fk.y);
            sv[r0 * 128 + i]       = siluf(fv.x);
            sv[(r0 + 1) * 128 + i] = siluf(fv.y);
        }
    }
    __syncthreads();

    // ---- phase 3: attention 1, separable Taylor, stride-16 i-mapping ----
    {
        const int row = t >> 4;      // 0..7
        const int js  = t & 15;      // 16 threads per row
        const float* kr = &sk[row * 128];
        const float* vr = &sv[row * 128];

        u64 S[NPOLY];
#pragma unroll
        for (int n = 0; n < NPOLY; n++) S[n] = 0;
#pragma unroll
        for (int u = 0; u < 8; u++) {
            float kk = kr[js + 16 * u];
            float vv = vr[js + 16 * u];
            u64 kk2 = pack2(kk, kk);
            u64 pv  = pack2(vv, 1.0f);   // (v*k^0, k^0)
            S[0] = add2(S[0], pv);
#pragma unroll
            for (int n = 1; n < NPOLY; n++) {
                pv = mul2(pv, kk2);      // (v*k^n, k^n)
                S[n] = add2(S[n], pv);
            }
        }
#pragma unroll
        for (int s = 8; s > 0; s >>= 1) {
#pragma unroll
            for (int n = 0; n < NPOLY; n++)
                S[n] = add2(S[n], __shfl_xor_sync(0xffffffffu, S[n], s));
        }
        u64 an[NPOLY];
#pragma unroll
        for (int n = 0; n < NPOLY; n++)
            an[n] = mul2(S[n], pack2(c_inv[n], c_inv[n]));

#pragma unroll
        for (int u = 0; u < 8; u++) {
            int ii = js + 16 * u;
            float qv = sq[row * 128 + ii];
            EVAL1(qv, shT[ii * HSTR + row])
        }
    }
    __syncthreads();

    // ---- phase 4: h2 = silu(attn1 @ W_h^T + b_h); bf16 weights ----
    {
        u64 a2[2];
        float bb = b_h[i2];
        a2[0] = a2[1] = pack2(bb, bb);
#pragma unroll 4
        for (int j = 0; j < 128; j++) {
            unsigned w = g_Whb[j * 64 + i2];
            u64 w2 = bfdup_lo(w);
            ulonglong2 hv = *(const ulonglong2*)&shT[j * HSTR + g4 * 4];
            ffma2(a2[0], w2, hv.x);
            ffma2(a2[1], w2, hv.y);
        }
        float2 f0 = unpack2(a2[0]), f1 = unpack2(a2[1]);
        float4 o = make_float4(siluf(f0.x), siluf(f0.y),
                               siluf(f1.x), siluf(f1.y));
        *(float4*)&sh2T[i2 * HSTR + g4 * 4] = o;
    }
    __syncthreads();

    // ---- phase 5: q2,k2,v2 (64x64 GEMMs); bf16 packed weights ----
    {
        u64 aq[2], ak[2], av[2];
        float bq = Bq2[i2], bk = Bk2[i2], bv = Bv2[i2];
        aq[0] = aq[1] = pack2(bq, bq);
        ak[0] = ak[1] = pack2(bk, bk);
        av[0] = av[1] = pack2(bv, bv);
#pragma unroll 4
        for (int j = 0; j < 64; j++) {
            uint2 wp = g_Wqkv2[j * 64 + i2];
            u64 wq2 = bfdup_lo(wp.x);
            u64 wk2 = bfdup_hi(wp.x);
            u64 wv2 = bfdup_lo(wp.y);
            ulonglong2 hv = *(const ulonglong2*)&sh2T[j * HSTR + g4 * 4];
            ffma2(aq[0], wq2, hv.x); ffma2(aq[1], wq2, hv.y);
            ffma2(ak[0], wk2, hv.x); ffma2(ak[1], wk2, hv.y);
            ffma2(av[0], wv2, hv.x); ffma2(av[1], wv2, hv.y);
        }
#pragma unroll
        for (int p = 0; p < 2; p++) {
            float2 fq = unpack2(aq[p]);
            float2 fk = unpack2(ak[p]);
            float2 fv = unpack2(av[p]);
            int r0 = g4 * 4 + 2 * p;
            sq[r0 * 64 + i2]       = siluf(fq.x);
            sq[(r0 + 1) * 64 + i2] = siluf(fq.y);
            sk[r0 * 64 + i2]       = siluf(fk.x);
            sk[(r0 + 1) * 64 + i2] = siluf(fk.y);
            sv[r0 * 64 + i2]       = siluf(fv.x);
            sv[(r0 + 1) * 64 + i2] = siluf(fv.y);
        }
    }
    __syncthreads();

    // ---- phase 6: attention 2, separable Taylor, stride-16 i-mapping ----
    {
        const int row = t >> 4;      // 0..7
        const int js  = t & 15;
        const float* kr = &sk[row * 64];
        const float* vr = &sv[row * 64];

        u64 S[NPOLY];
#pragma unroll
        for (int n = 0; n < NPOLY; n++) S[n] = 0;
#pragma unroll
        for (int u = 0; u < 4; u++) {
            float kk = kr[js + 16 * u];
            float vv = vr[js + 16 * u];
            u64 kk2 = pack2(kk, kk);
            u64 pv  = pack2(vv, 1.0f);
            S[0] = add2(S[0], pv);
#pragma unroll
            for (int n = 1; n < NPOLY; n++) {
                pv = mul2(pv, kk2);
                S[n] = add2(S[n], pv);
            }
        }
#pragma unroll
        for (int s = 8; s > 0; s >>= 1) {
#pragma unroll
            for (int n = 0; n < NPOLY; n++)
                S[n] = add2(S[n], __shfl_xor_sync(0xffffffffu, S[n], s));
        }
        u64 an[NPOLY];
#pragma unroll
        for (int n = 0; n < NPOLY; n++)
            an[n] = mul2(S[n], pack2(c_inv[n], c_inv[n]));

#pragma unroll
        for (int u = 0; u < 4; u++) {
            int ii = js + 16 * u;
            float qv = sq[row * 64 + ii];
            EVAL1(qv, sAt2[row * 64 + ii])
        }
    }
    __syncthreads();

    // ---- phase 7: y = silu(attn2 @ W_out^T + b_out) ----
    for (int idx = t; idx < RPB * 25; idx += NTHREADS) {
        int r = idx / 25;
        int o = idx - r * 25;
        float acc = b_out[o];
        const float4* wrow = (const float4*)&g_WoutT[o * 64];
        const float4* arow = (const float4*)&sAt2[r * 64];
#pragma unroll
        for (int j = 0; j < 16; j++) {
            float4 w = wrow[j];
            float4 a = arow[j];
            acc += w.x * a.x + w.y * a.y + w.z * a.z + w.w * a.w;
        }
        sy[idx] = siluf(acc);
    }
    __syncthreads();

    // ---- phase 8: quadratic-form reduction ----
    if (t < RPB) {
        const float* y = &sy[t * 25];
        float M11 = 0.f, M12 = 0.f, M21 = 0.f, M22 = 0.f, Mpp = 0.f;
#pragma unroll
        for (int j = 0; j < 5; j++) {
            M11 += y[j] * y[j];
            M12 += y[5 + j] * y[5 + j];
            M21 += y[10 + j] * y[10 + j];
            M22 += y[15 + j] * y[15 + j];
            Mpp += y[20 + j] * y[20 + j];
        }
        float q0 = y[0], q1 = y[1], qq2 = y[2], q3 = y[3];
        float quad = M11 * (q0 * q0 + q1 * q1)
                   + (M12 + M21) * (q0 * qq2 + q1 * q3)
                   + M22 * (qq2 * qq2 + q3 * q3);
        out[row0 + t] = quad + Mpp;
    }
}

extern "C" void kernel_launch(void* const* d_in, const int* in_sizes, int n_in,
                              void* d_out, int out_size) {
    const float* x     = (const float*)d_in[0];
    const float* W_in  = (const float*)d_in[2];
    const float* b_in  = (const float*)d_in[3];
    const float* Aq4   = (const float*)d_in[4];
    const float* Bq4   = (const float*)d_in[5];
    const float* Ak4   = (const float*)d_in[6];
    const float* Bk4   = (const float*)d_in[7];
    const float* Av4   = (const float*)d_in[8];
    const float* Bv4   = (const float*)d_in[9];
    const float* W_h   = (const float*)d_in[10];
    const float* b_h   = (const float*)d_in[11];
    const float* Aq7   = (const float*)d_in[12];
    const float* Bq7   = (const float*)d_in[13];
    const float* Ak7   = (const float*)d_in[14];
    const float* Bk7   = (const float*)d_in[15];
    const float* Av7   = (const float*)d_in[16];
    const float* Bv7   = (const float*)d_in[17];
    const float* W_out = (const float*)d_in[18];
    const float* b_out = (const float*)d_in[19];

    int nrows = in_sizes[0] / 12;

    prep_weights<<<64, 256>>>(W_in, Aq4, Ak4, Av4, W_h, Aq7, Ak7, Av7, W_out);
    lemurs_fused<<<nrows / RPB, NTHREADS>>>(x, b_in, Bq4, Bk4, Bv4,
                                            b_h, Bq7, Bk7, Bv7,
                                            b_out, (float*)d_out);
}